// round 3
// baseline (speedup 1.0000x reference)
#include <cuda_runtime.h>
#include <cuda_bf16.h>
#include <cstdint>

// Problem constants
static constexpr int NN = 50000;   // nodes
static constexpr int EE = 800000;  // edges
static constexpr int HH = 160;     // hidden
static constexpr float LEAK = 0.01f;

// ---------------- device scratch (allocation-free rule) ----------------
__device__ float g_t[NN * HH];          // encoder concat output
__device__ float g_hA[NN * HH];
__device__ float g_hB[NN * HH];
__device__ float g_mean[2 * NN * HH];   // per-relation aggregated means
__device__ int   g_deg[2 * NN];
__device__ int   g_off[2 * NN + 1];
__device__ int   g_cur[2 * NN];
__device__ int   g_elist[EE];

// ---------------- CSR build ----------------
__global__ void k_zero_deg() {
    int i = blockIdx.x * blockDim.x + threadIdx.x;
    if (i < 2 * NN) g_deg[i] = 0;
}

__global__ void k_count(const int* __restrict__ ei, const int* __restrict__ et) {
    int e = blockIdx.x * blockDim.x + threadIdx.x;
    if (e >= EE) return;
    int d = ei[EE + e];
    int r = et[e];
    atomicAdd(&g_deg[r * NN + d], 1);
}

// single-block exclusive scan over 2N counts -> g_off, g_cur
__global__ void k_scan() {
    __shared__ int sdata[1024];
    __shared__ int carry;
    int tid = threadIdx.x;
    if (tid == 0) carry = 0;
    __syncthreads();
    const int TOT = 2 * NN;
    for (int base = 0; base < TOT; base += 1024) {
        int i = base + tid;
        int v = (i < TOT) ? g_deg[i] : 0;
        sdata[tid] = v;
        __syncthreads();
        // inclusive scan
        #pragma unroll
        for (int off = 1; off < 1024; off <<= 1) {
            int t = (tid >= off) ? sdata[tid - off] : 0;
            __syncthreads();
            sdata[tid] += t;
            __syncthreads();
        }
        int inc = sdata[tid];
        int excl = carry + inc - v;
        if (i < TOT) { g_off[i] = excl; g_cur[i] = excl; }
        __syncthreads();
        if (tid == 1023) carry += sdata[1023];
        __syncthreads();
    }
    if (tid == 0) g_off[TOT] = carry;
}

__global__ void k_fill(const int* __restrict__ ei, const int* __restrict__ et) {
    int e = blockIdx.x * blockDim.x + threadIdx.x;
    if (e >= EE) return;
    int s = ei[e];
    int d = ei[EE + e];
    int r = et[e];
    int pos = atomicAdd(&g_cur[r * NN + d], 1);
    g_elist[pos] = s;
}

// ---------------- gather (per-relation segment mean) ----------------
// one warp per (relation,node) pair p = r*NN + node
__global__ void k_gather(const float* __restrict__ h, float* __restrict__ mean) {
    int w = (blockIdx.x * blockDim.x + threadIdx.x) >> 5;
    int lane = threadIdx.x & 31;
    if (w >= 2 * NN) return;
    int beg = g_off[w], end = g_off[w + 1];
    float a0 = 0.f, a1 = 0.f, a2 = 0.f, a3 = 0.f, a4 = 0.f;
    for (int k = beg; k < end; k++) {
        int s = g_elist[k];
        const float* hp = h + (size_t)s * HH + lane;
        a0 += hp[0];
        a1 += hp[32];
        a2 += hp[64];
        a3 += hp[96];
        a4 += hp[128];
    }
    int deg = end - beg;
    float inv = deg > 0 ? 1.f / (float)deg : 0.f;
    float* o = mean + (size_t)w * HH + lane;
    o[0]  = a0 * inv;
    o[32] = a1 * inv;
    o[64] = a2 * inv;
    o[96] = a3 * inv;
    o[128] = a4 * inv;
}

// ---------------- fused multi-term GEMM ----------------
// C[:, cbase:cbase+BN] = act( sum_t A_t[M,K] @ W_t[K,BN] + bias )
// BM=128, BK=32, 256 threads, each thread computes 8 rows x (BN/16) cols.
template <int BN, bool RELU>
__global__ __launch_bounds__(256) void gemm_kernel(
    const float* __restrict__ A0, const float* __restrict__ W0,
    const float* __restrict__ A1, const float* __restrict__ W1,
    const float* __restrict__ A2, const float* __restrict__ W2,
    const float* __restrict__ bias, float* __restrict__ C,
    int M, int K, int ldC, int cbase, int nterms)
{
    constexpr int BM = 128;
    constexpr int BK = 32;
    constexpr int TM = 8;
    constexpr int TN = BN / 16;

    __shared__ __align__(16) float As[BM][BK + 1];
    __shared__ __align__(16) float Ws[BK][BN];

    const int tid = threadIdx.x;
    const int tx = tid & 15;         // col group
    const int ty = tid >> 4;         // row group
    const int rowbase = blockIdx.x * BM;
    const bool vec = (K % 4 == 0);

    float acc[TM][TN];
    #pragma unroll
    for (int i = 0; i < TM; i++)
        #pragma unroll
        for (int j = 0; j < TN; j++) acc[i][j] = 0.f;

    for (int term = 0; term < nterms; term++) {
        const float* A = (term == 0) ? A0 : (term == 1) ? A1 : A2;
        const float* W = (term == 0) ? W0 : (term == 1) ? W1 : W2;

        for (int kt = 0; kt < K; kt += BK) {
            // load A tile [BM x BK]
            if (vec) {
                #pragma unroll
                for (int p = 0; p < 4; p++) {
                    int idx = tid + 256 * p;      // 1024 float4 slots
                    int row = idx >> 3;
                    int kq  = idx & 7;
                    int gr = rowbase + row;
                    int gk = kt + kq * 4;
                    float4 v = make_float4(0.f, 0.f, 0.f, 0.f);
                    if (gr < M && gk < K)
                        v = *reinterpret_cast<const float4*>(A + (size_t)gr * K + gk);
                    As[row][kq * 4 + 0] = v.x;
                    As[row][kq * 4 + 1] = v.y;
                    As[row][kq * 4 + 2] = v.z;
                    As[row][kq * 4 + 3] = v.w;
                }
            } else {
                for (int idx = tid; idx < BM * BK; idx += 256) {
                    int row = idx >> 5;
                    int kk = idx & 31;
                    int gr = rowbase + row;
                    int gk = kt + kk;
                    As[row][kk] = (gr < M && gk < K) ? A[(size_t)gr * K + gk] : 0.f;
                }
            }
            // load W tile [BK x BN]
            for (int idx = tid; idx < 8 * BN; idx += 256) {   // BK*BN/4 float4s
                int wrow = idx / (BN / 4);
                int wc = idx % (BN / 4);
                int gk = kt + wrow;
                float4 v = make_float4(0.f, 0.f, 0.f, 0.f);
                if (gk < K)
                    v = *reinterpret_cast<const float4*>(W + (size_t)gk * BN + wc * 4);
                *reinterpret_cast<float4*>(&Ws[wrow][wc * 4]) = v;
            }
            __syncthreads();

            #pragma unroll 4
            for (int kk = 0; kk < BK; kk++) {
                float a[TM];
                #pragma unroll
                for (int i = 0; i < TM; i++) a[i] = As[ty * TM + i][kk];
                float w[TN];
                #pragma unroll
                for (int j = 0; j < TN; j++) w[j] = Ws[kk][tx + 16 * j];
                #pragma unroll
                for (int i = 0; i < TM; i++)
                    #pragma unroll
                    for (int j = 0; j < TN; j++) acc[i][j] += a[i] * w[j];
            }
            __syncthreads();
        }
    }

    // epilogue
    #pragma unroll
    for (int j = 0; j < TN; j++) {
        int c = tx + 16 * j;
        float bv = bias[c];
        #pragma unroll
        for (int i = 0; i < TM; i++) {
            int row = rowbase + ty * TM + i;
            if (row < M) {
                float v = acc[i][j] + bv;
                if (RELU) v = (v >= 0.f) ? v : LEAK * v;
                C[(size_t)row * ldC + cbase + c] = v;
            }
        }
    }
}

// ---------------- final tiny head: out = em @ W_o2 + b_o2 ----------------
__global__ void k_out2(const float* __restrict__ em, const float* __restrict__ W2,
                       const float* __restrict__ b2, float* __restrict__ out) {
    __shared__ float es[64 * 80];
    int nb = blockIdx.x * 64;
    for (int idx = threadIdx.x; idx < 64 * 80; idx += 256) {
        int n = nb + idx / 80;
        es[idx] = (n < NN) ? em[(size_t)n * 80 + idx % 80] : 0.f;
    }
    __syncthreads();
    int t = threadIdx.x;
    if (t < 128) {
        int ln = t >> 1;
        int c = t & 1;
        int n = nb + ln;
        if (n < NN) {
            float s = b2[c];
            #pragma unroll 8
            for (int k = 0; k < 80; k++) s += es[ln * 80 + k] * W2[k * 2 + c];
            out[(size_t)n * 2 + c] = s;
        }
    }
}

// ---------------- launch ----------------
extern "C" void kernel_launch(void* const* d_in, const int* in_sizes, int n_in,
                              void* d_out, int out_size) {
    const float* pre_x   = (const float*)d_in[0];
    const int*   ei      = (const int*)d_in[2];
    const int*   et      = (const int*)d_in[3];
    const float* numprop = (const float*)d_in[4];
    const float* numcat  = (const float*)d_in[5];
    const float* des     = (const float*)d_in[6];
    const float* tweet   = (const float*)d_in[7];
    const float* W_np = (const float*)d_in[8],  *b_np = (const float*)d_in[9];
    const float* W_nc = (const float*)d_in[10], *b_nc = (const float*)d_in[11];
    const float* W_des = (const float*)d_in[12], *b_des = (const float*)d_in[13];
    const float* W_text = (const float*)d_in[14], *b_text = (const float*)d_in[15];
    const float* W_tweet = (const float*)d_in[16], *b_tweet = (const float*)d_in[17];
    const float* W_in = (const float*)d_in[18], *b_in = (const float*)d_in[19];
    const float* W_rel1 = (const float*)d_in[20];
    const float* W_root1 = (const float*)d_in[21], *b_conv1 = (const float*)d_in[22];
    const float* W_rel2 = (const float*)d_in[23];
    const float* W_root2 = (const float*)d_in[24], *b_conv2 = (const float*)d_in[25];
    const float* W_o1 = (const float*)d_in[26], *b_o1 = (const float*)d_in[27];
    const float* W_o2 = (const float*)d_in[28], *b_o2 = (const float*)d_in[29];

    float* t;    cudaGetSymbolAddress((void**)&t, g_t);
    float* hA;   cudaGetSymbolAddress((void**)&hA, g_hA);
    float* hB;   cudaGetSymbolAddress((void**)&hB, g_hB);
    float* mean; cudaGetSymbolAddress((void**)&mean, g_mean);

    float* out = (float*)d_out;            // [N,2]
    float* em = out + 2 * (size_t)NN;      // [N,80]

    // CSR build (edges static -> built once per replay, reused by both layers)
    k_zero_deg<<<(2 * NN + 255) / 256, 256>>>();
    k_count<<<(EE + 255) / 256, 256>>>(ei, et);
    k_scan<<<1, 1024>>>();
    k_fill<<<(EE + 255) / 256, 256>>>(ei, et);

    dim3 gM((NN + 127) / 128);

    // encoders -> g_t (concat layout: np | nc | des | tweet@W_text | pre_x@W_tweet)
    gemm_kernel<32, true><<<gM, 256>>>(numprop, W_np, nullptr, nullptr, nullptr, nullptr,
                                       b_np, t, NN, 6, HH, 0, 1);
    gemm_kernel<32, true><<<gM, 256>>>(numcat, W_nc, nullptr, nullptr, nullptr, nullptr,
                                       b_nc, t, NN, 11, HH, 32, 1);
    gemm_kernel<32, true><<<gM, 256>>>(des, W_des, nullptr, nullptr, nullptr, nullptr,
                                       b_des, t, NN, 768, HH, 64, 1);
    gemm_kernel<32, true><<<gM, 256>>>(tweet, W_text, nullptr, nullptr, nullptr, nullptr,
                                       b_text, t, NN, 768, HH, 96, 1);
    gemm_kernel<32, true><<<gM, 256>>>(pre_x, W_tweet, nullptr, nullptr, nullptr, nullptr,
                                       b_tweet, t, NN, 768, HH, 128, 1);

    // h = leaky(t @ W_in + b_in)
    gemm_kernel<160, true><<<gM, 256>>>(t, W_in, nullptr, nullptr, nullptr, nullptr,
                                        b_in, hA, NN, HH, HH, 0, 1);

    // conv1: hB = hA@W_root1 + mean0@W_rel1[0] + mean1@W_rel1[1] + b_conv1
    k_gather<<<(2 * NN * 32 + 255) / 256, 256>>>(hA, mean);
    gemm_kernel<160, false><<<gM, 256>>>(hA, W_root1,
                                         mean, W_rel1,
                                         mean + (size_t)NN * HH, W_rel1 + HH * HH,
                                         b_conv1, hB, NN, HH, HH, 0, 3);

    // conv2
    k_gather<<<(2 * NN * 32 + 255) / 256, 256>>>(hB, mean);
    gemm_kernel<160, false><<<gM, 256>>>(hB, W_root2,
                                         mean, W_rel2,
                                         mean + (size_t)NN * HH, W_rel2 + HH * HH,
                                         b_conv2, hA, NN, HH, HH, 0, 3);

    // em = leaky(h @ W_o1 + b_o1), written straight to d_out tail
    gemm_kernel<80, true><<<gM, 256>>>(hA, W_o1, nullptr, nullptr, nullptr, nullptr,
                                       b_o1, em, NN, HH, 80, 0, 1);

    // out = em @ W_o2 + b_o2
    k_out2<<<(NN + 63) / 64, 256>>>(em, W_o2, b_o2, out);
}

// round 4
// speedup vs baseline: 1.0780x; 1.0780x over previous
#include <cuda_runtime.h>
#include <cuda_bf16.h>
#include <cstdint>

// Problem constants
static constexpr int NN = 50000;   // nodes
static constexpr int EE = 800000;  // edges
static constexpr int HH = 160;     // hidden
static constexpr float LEAK = 0.01f;

// ---------------- device scratch (allocation-free rule) ----------------
__device__ float g_t[NN * HH];          // encoder concat output
__device__ float g_hA[NN * HH];
__device__ float g_hB[NN * HH];
__device__ float g_mean[2 * NN * HH];   // per-relation aggregated means
__device__ int   g_deg[2 * NN];
__device__ int   g_off[2 * NN + 1];
__device__ int   g_cur[2 * NN];
__device__ int   g_elist[EE];

// ---------------- f32x2 packed-math helpers ----------------
__device__ __forceinline__ void ffma2(unsigned long long& d,
                                      unsigned long long a,
                                      unsigned long long b) {
    asm("fma.rn.f32x2 %0, %1, %2, %0;" : "+l"(d) : "l"(a), "l"(b));
}
__device__ __forceinline__ unsigned long long dup2(float x) {
    unsigned long long r;
    asm("mov.b64 %0, {%1, %1};" : "=l"(r) : "f"(x));
    return r;
}
__device__ __forceinline__ float2 unpk2(unsigned long long v) {
    float2 r;
    asm("mov.b64 {%0, %1}, %2;" : "=f"(r.x), "=f"(r.y) : "l"(v));
    return r;
}

// ---------------- CSR build ----------------
__global__ void k_zero_deg() {
    int i = blockIdx.x * blockDim.x + threadIdx.x;
    if (i < 2 * NN) g_deg[i] = 0;
}

__global__ void k_count(const int* __restrict__ ei, const int* __restrict__ et) {
    int e = blockIdx.x * blockDim.x + threadIdx.x;
    if (e >= EE) return;
    int d = ei[EE + e];
    int r = et[e];
    atomicAdd(&g_deg[r * NN + d], 1);
}

// single-block exclusive scan over 2N counts -> g_off, g_cur (shuffle scan)
__global__ void k_scan() {
    __shared__ int warpsum[32];
    __shared__ int carry_s;
    const int TOT = 2 * NN;
    int tid = threadIdx.x;
    int lane = tid & 31;
    int wid = tid >> 5;
    if (tid == 0) carry_s = 0;
    __syncthreads();
    for (int base = 0; base < TOT; base += 1024) {
        int i = base + tid;
        int v = (i < TOT) ? g_deg[i] : 0;
        int incl = v;
        #pragma unroll
        for (int o = 1; o < 32; o <<= 1) {
            int t = __shfl_up_sync(0xFFFFFFFFu, incl, o);
            if (lane >= o) incl += t;
        }
        if (lane == 31) warpsum[wid] = incl;
        __syncthreads();
        if (wid == 0) {
            int s = warpsum[lane];
            int si = s;
            #pragma unroll
            for (int o = 1; o < 32; o <<= 1) {
                int t = __shfl_up_sync(0xFFFFFFFFu, si, o);
                if (lane >= o) si += t;
            }
            warpsum[lane] = si - s;   // exclusive warp offsets
        }
        __syncthreads();
        int excl = incl - v + warpsum[wid];
        int out = carry_s + excl;
        if (i < TOT) { g_off[i] = out; g_cur[i] = out; }
        __syncthreads();
        if (tid == 1023) carry_s = out + v;
        __syncthreads();
    }
    if (tid == 0) g_off[TOT] = carry_s;
}

__global__ void k_fill(const int* __restrict__ ei, const int* __restrict__ et) {
    int e = blockIdx.x * blockDim.x + threadIdx.x;
    if (e >= EE) return;
    int s = ei[e];
    int d = ei[EE + e];
    int r = et[e];
    int pos = atomicAdd(&g_cur[r * NN + d], 1);
    g_elist[pos] = s;
}

// ---------------- gather (per-relation segment mean), float4 loads ----------------
// one warp per (relation,node) pair w = r*NN + node
__global__ void k_gather(const float* __restrict__ h, float* __restrict__ mean) {
    int w = (blockIdx.x * blockDim.x + threadIdx.x) >> 5;
    int lane = threadIdx.x & 31;
    if (w >= 2 * NN) return;
    int beg = g_off[w], end = g_off[w + 1];
    float4 a0 = make_float4(0.f, 0.f, 0.f, 0.f);
    float4 a1 = a0;
    const bool tail = (lane < 8);
    #pragma unroll 2
    for (int k = beg; k < end; k++) {
        int s = g_elist[k];
        const float4* hp = reinterpret_cast<const float4*>(h + (size_t)s * HH);
        float4 v = __ldg(&hp[lane]);
        a0.x += v.x; a0.y += v.y; a0.z += v.z; a0.w += v.w;
        if (tail) {
            float4 u = __ldg(&hp[32 + lane]);
            a1.x += u.x; a1.y += u.y; a1.z += u.z; a1.w += u.w;
        }
    }
    int deg = end - beg;
    float inv = (deg > 0) ? 1.f / (float)deg : 0.f;
    a0.x *= inv; a0.y *= inv; a0.z *= inv; a0.w *= inv;
    float4* o = reinterpret_cast<float4*>(mean + (size_t)w * HH);
    o[lane] = a0;
    if (tail) {
        a1.x *= inv; a1.y *= inv; a1.z *= inv; a1.w *= inv;
        o[32 + lane] = a1;
    }
}

// ---------------- fused multi-term GEMM (f32x2 packed inner loop) ----------------
// C[:, cbase:cbase+BN] = act( sum_t A_t[M,K] @ W_t[K,BN] + bias )
// BM=128, BK=32, 256 threads. CT column-threads, each owns TNP column-pairs.
template <int BN, int CT, bool RELU>
__global__ __launch_bounds__(256) void gemm_kernel(
    const float* __restrict__ A0, const float* __restrict__ W0,
    const float* __restrict__ A1, const float* __restrict__ W1,
    const float* __restrict__ A2, const float* __restrict__ W2,
    const float* __restrict__ bias, float* __restrict__ C,
    int M, int K, int ldC, int cbase, int nterms)
{
    constexpr int BM = 128;
    constexpr int BK = 32;
    constexpr int RT = 256 / CT;        // row-threads
    constexpr int TM = BM / RT;         // rows per thread
    constexpr int TNP = BN / (2 * CT);  // column-pairs per thread
    static_assert(BN % (2 * CT) == 0, "pair layout");

    __shared__ __align__(16) float As[BM][BK + 1];
    __shared__ __align__(16) float Ws[BK][BN];

    const int tid = threadIdx.x;
    const int tx = tid % CT;
    const int ty = tid / CT;
    const int rowbase = blockIdx.x * BM;
    const bool vec = (K % 32 == 0);

    unsigned long long acc[TM][TNP];
    #pragma unroll
    for (int i = 0; i < TM; i++)
        #pragma unroll
        for (int p = 0; p < TNP; p++) acc[i][p] = 0ULL;

    for (int term = 0; term < nterms; term++) {
        const float* A = (term == 0) ? A0 : (term == 1) ? A1 : A2;
        const float* W = (term == 0) ? W0 : (term == 1) ? W1 : W2;

        for (int kt = 0; kt < K; kt += BK) {
            // load A tile [BM x BK]
            if (vec) {
                #pragma unroll
                for (int p = 0; p < 4; p++) {
                    int idx = tid + 256 * p;      // 1024 float4 slots
                    int row = idx >> 3;
                    int kq  = idx & 7;
                    int gr = rowbase + row;
                    float4 v = make_float4(0.f, 0.f, 0.f, 0.f);
                    if (gr < M)
                        v = *reinterpret_cast<const float4*>(A + (size_t)gr * K + kt + kq * 4);
                    As[row][kq * 4 + 0] = v.x;
                    As[row][kq * 4 + 1] = v.y;
                    As[row][kq * 4 + 2] = v.z;
                    As[row][kq * 4 + 3] = v.w;
                }
            } else {
                for (int idx = tid; idx < BM * BK; idx += 256) {
                    int row = idx >> 5;
                    int kk = idx & 31;
                    int gr = rowbase + row;
                    int gk = kt + kk;
                    As[row][kk] = (gr < M && gk < K) ? A[(size_t)gr * K + gk] : 0.f;
                }
            }
            // load W tile [BK x BN]
            for (int idx = tid; idx < 8 * BN; idx += 256) {   // BK*BN/4 float4s
                int wrow = idx / (BN / 4);
                int wc = idx % (BN / 4);
                int gk = kt + wrow;
                float4 v = make_float4(0.f, 0.f, 0.f, 0.f);
                if (gk < K)
                    v = *reinterpret_cast<const float4*>(W + (size_t)gk * BN + wc * 4);
                *reinterpret_cast<float4*>(&Ws[wrow][wc * 4]) = v;
            }
            __syncthreads();

            #pragma unroll 4
            for (int kk = 0; kk < BK; kk++) {
                unsigned long long w2[TNP];
                #pragma unroll
                for (int p = 0; p < TNP; p++)
                    w2[p] = *reinterpret_cast<const unsigned long long*>(
                                &Ws[kk][2 * tx + p * 2 * CT]);
                unsigned long long a2[TM];
                #pragma unroll
                for (int i = 0; i < TM; i++) a2[i] = dup2(As[ty * TM + i][kk]);
                #pragma unroll
                for (int i = 0; i < TM; i++)
                    #pragma unroll
                    for (int p = 0; p < TNP; p++)
                        ffma2(acc[i][p], a2[i], w2[p]);
            }
            __syncthreads();
        }
    }

    // epilogue (float2 stores)
    #pragma unroll
    for (int p = 0; p < TNP; p++) {
        int c0 = 2 * tx + p * 2 * CT;
        float bx = bias[c0];
        float by = bias[c0 + 1];
        #pragma unroll
        for (int i = 0; i < TM; i++) {
            int row = rowbase + ty * TM + i;
            if (row < M) {
                float2 v = unpk2(acc[i][p]);
                v.x += bx; v.y += by;
                if (RELU) {
                    v.x = (v.x >= 0.f) ? v.x : LEAK * v.x;
                    v.y = (v.y >= 0.f) ? v.y : LEAK * v.y;
                }
                *reinterpret_cast<float2*>(C + (size_t)row * ldC + cbase + c0) = v;
            }
        }
    }
}

// ---------------- final tiny head: out = em @ W_o2 + b_o2 ----------------
__global__ void k_out2(const float* __restrict__ em, const float* __restrict__ W2,
                       const float* __restrict__ b2, float* __restrict__ out) {
    __shared__ float es[64 * 80];
    int nb = blockIdx.x * 64;
    for (int idx = threadIdx.x; idx < 64 * 80; idx += 256) {
        int n = nb + idx / 80;
        es[idx] = (n < NN) ? em[(size_t)n * 80 + idx % 80] : 0.f;
    }
    __syncthreads();
    int t = threadIdx.x;
    if (t < 128) {
        int ln = t >> 1;
        int c = t & 1;
        int n = nb + ln;
        if (n < NN) {
            float s = b2[c];
            #pragma unroll 8
            for (int k = 0; k < 80; k++) s += es[ln * 80 + k] * W2[k * 2 + c];
            out[(size_t)n * 2 + c] = s;
        }
    }
}

// ---------------- launch ----------------
extern "C" void kernel_launch(void* const* d_in, const int* in_sizes, int n_in,
                              void* d_out, int out_size) {
    const float* pre_x   = (const float*)d_in[0];
    const int*   ei      = (const int*)d_in[2];
    const int*   et      = (const int*)d_in[3];
    const float* numprop = (const float*)d_in[4];
    const float* numcat  = (const float*)d_in[5];
    const float* des     = (const float*)d_in[6];
    const float* tweet   = (const float*)d_in[7];
    const float* W_np = (const float*)d_in[8],  *b_np = (const float*)d_in[9];
    const float* W_nc = (const float*)d_in[10], *b_nc = (const float*)d_in[11];
    const float* W_des = (const float*)d_in[12], *b_des = (const float*)d_in[13];
    const float* W_text = (const float*)d_in[14], *b_text = (const float*)d_in[15];
    const float* W_tweet = (const float*)d_in[16], *b_tweet = (const float*)d_in[17];
    const float* W_in = (const float*)d_in[18], *b_in = (const float*)d_in[19];
    const float* W_rel1 = (const float*)d_in[20];
    const float* W_root1 = (const float*)d_in[21], *b_conv1 = (const float*)d_in[22];
    const float* W_rel2 = (const float*)d_in[23];
    const float* W_root2 = (const float*)d_in[24], *b_conv2 = (const float*)d_in[25];
    const float* W_o1 = (const float*)d_in[26], *b_o1 = (const float*)d_in[27];
    const float* W_o2 = (const float*)d_in[28], *b_o2 = (const float*)d_in[29];

    float* t;    cudaGetSymbolAddress((void**)&t, g_t);
    float* hA;   cudaGetSymbolAddress((void**)&hA, g_hA);
    float* hB;   cudaGetSymbolAddress((void**)&hB, g_hB);
    float* mean; cudaGetSymbolAddress((void**)&mean, g_mean);

    float* out = (float*)d_out;            // [N,2]
    float* em = out + 2 * (size_t)NN;      // [N,80]

    // CSR build (edges static -> rebuilt every replay, reused by both layers)
    k_zero_deg<<<(2 * NN + 255) / 256, 256>>>();
    k_count<<<(EE + 255) / 256, 256>>>(ei, et);
    k_scan<<<1, 1024>>>();
    k_fill<<<(EE + 255) / 256, 256>>>(ei, et);

    dim3 gM((NN + 127) / 128);

    // encoders -> g_t (concat layout: np | nc | des | tweet@W_text | pre_x@W_tweet)
    gemm_kernel<32, 16, true><<<gM, 256>>>(numprop, W_np, nullptr, nullptr, nullptr, nullptr,
                                           b_np, t, NN, 6, HH, 0, 1);
    gemm_kernel<32, 16, true><<<gM, 256>>>(numcat, W_nc, nullptr, nullptr, nullptr, nullptr,
                                           b_nc, t, NN, 11, HH, 32, 1);
    gemm_kernel<32, 16, true><<<gM, 256>>>(des, W_des, nullptr, nullptr, nullptr, nullptr,
                                           b_des, t, NN, 768, HH, 64, 1);
    gemm_kernel<32, 16, true><<<gM, 256>>>(tweet, W_text, nullptr, nullptr, nullptr, nullptr,
                                           b_text, t, NN, 768, HH, 96, 1);
    gemm_kernel<32, 16, true><<<gM, 256>>>(pre_x, W_tweet, nullptr, nullptr, nullptr, nullptr,
                                           b_tweet, t, NN, 768, HH, 128, 1);

    // h = leaky(t @ W_in + b_in)
    gemm_kernel<160, 16, true><<<gM, 256>>>(t, W_in, nullptr, nullptr, nullptr, nullptr,
                                            b_in, hA, NN, HH, HH, 0, 1);

    // conv1: hB = hA@W_root1 + mean0@W_rel1[0] + mean1@W_rel1[1] + b_conv1
    k_gather<<<(2 * NN * 32 + 255) / 256, 256>>>(hA, mean);
    gemm_kernel<160, 16, false><<<gM, 256>>>(hA, W_root1,
                                             mean, W_rel1,
                                             mean + (size_t)NN * HH, W_rel1 + HH * HH,
                                             b_conv1, hB, NN, HH, HH, 0, 3);

    // conv2
    k_gather<<<(2 * NN * 32 + 255) / 256, 256>>>(hB, mean);
    gemm_kernel<160, 16, false><<<gM, 256>>>(hB, W_root2,
                                             mean, W_rel2,
                                             mean + (size_t)NN * HH, W_rel2 + HH * HH,
                                             b_conv2, hA, NN, HH, HH, 0, 3);

    // em = leaky(h @ W_o1 + b_o1), written straight to d_out tail
    gemm_kernel<80, 8, true><<<gM, 256>>>(hA, W_o1, nullptr, nullptr, nullptr, nullptr,
                                          b_o1, em, NN, HH, 80, 0, 1);

    // out = em @ W_o2 + b_o2
    k_out2<<<(NN + 63) / 64, 256>>>(em, W_o2, b_o2, out);
}

// round 6
// speedup vs baseline: 1.5835x; 1.4690x over previous
#include <cuda_runtime.h>
#include <cuda_bf16.h>
#include <mma.h>
#include <cstdint>

using namespace nvcuda;

// Problem constants
static constexpr int NN = 50000;   // nodes
static constexpr int EE = 800000;  // edges
static constexpr int HH = 160;     // hidden
static constexpr float LEAK = 0.01f;

// ---------------- device scratch (allocation-free rule) ----------------
__device__ float g_t[NN * HH];          // encoder concat output
__device__ float g_hA[NN * HH];
__device__ float g_hB[NN * HH];
__device__ float g_mean[2 * NN * HH];   // per-relation aggregated means
__device__ int   g_deg[2 * NN];
__device__ int   g_off[2 * NN + 1];
__device__ int   g_cur[2 * NN];
__device__ int   g_elist[EE];

// ---------------- CSR build ----------------
__global__ void k_zero_deg() {
    int i = blockIdx.x * blockDim.x + threadIdx.x;
    if (i < 2 * NN) g_deg[i] = 0;
}

__global__ void k_count(const int* __restrict__ ei, const int* __restrict__ et) {
    int e = blockIdx.x * blockDim.x + threadIdx.x;
    if (e >= EE) return;
    int d = ei[EE + e];
    int r = et[e];
    atomicAdd(&g_deg[r * NN + d], 1);
}

__global__ void k_scan() {
    __shared__ int warpsum[32];
    __shared__ int carry_s;
    const int TOT = 2 * NN;
    int tid = threadIdx.x;
    int lane = tid & 31;
    int wid = tid >> 5;
    if (tid == 0) carry_s = 0;
    __syncthreads();
    for (int base = 0; base < TOT; base += 1024) {
        int i = base + tid;
        int v = (i < TOT) ? g_deg[i] : 0;
        int incl = v;
        #pragma unroll
        for (int o = 1; o < 32; o <<= 1) {
            int t = __shfl_up_sync(0xFFFFFFFFu, incl, o);
            if (lane >= o) incl += t;
        }
        if (lane == 31) warpsum[wid] = incl;
        __syncthreads();
        if (wid == 0) {
            int s = warpsum[lane];
            int si = s;
            #pragma unroll
            for (int o = 1; o < 32; o <<= 1) {
                int t = __shfl_up_sync(0xFFFFFFFFu, si, o);
                if (lane >= o) si += t;
            }
            warpsum[lane] = si - s;
        }
        __syncthreads();
        int excl = incl - v + warpsum[wid];
        int out = carry_s + excl;
        if (i < TOT) { g_off[i] = out; g_cur[i] = out; }
        __syncthreads();
        if (tid == 1023) carry_s = out + v;
        __syncthreads();
    }
    if (tid == 0) g_off[TOT] = carry_s;
}

__global__ void k_fill(const int* __restrict__ ei, const int* __restrict__ et) {
    int e = blockIdx.x * blockDim.x + threadIdx.x;
    if (e >= EE) return;
    int s = ei[e];
    int d = ei[EE + e];
    int r = et[e];
    int pos = atomicAdd(&g_cur[r * NN + d], 1);
    g_elist[pos] = s;
}

// ---------------- gather (per-relation segment mean) ----------------
__global__ void k_gather(const float* __restrict__ h, float* __restrict__ mean) {
    int w = (blockIdx.x * blockDim.x + threadIdx.x) >> 5;
    int lane = threadIdx.x & 31;
    if (w >= 2 * NN) return;
    int beg = g_off[w], end = g_off[w + 1];
    float4 a0 = make_float4(0.f, 0.f, 0.f, 0.f);
    float4 a1 = a0;
    const bool tail = (lane < 8);
    #pragma unroll 2
    for (int k = beg; k < end; k++) {
        int s = g_elist[k];
        const float4* hp = reinterpret_cast<const float4*>(h + (size_t)s * HH);
        float4 v = __ldg(&hp[lane]);
        a0.x += v.x; a0.y += v.y; a0.z += v.z; a0.w += v.w;
        if (tail) {
            float4 u = __ldg(&hp[32 + lane]);
            a1.x += u.x; a1.y += u.y; a1.z += u.z; a1.w += u.w;
        }
    }
    int deg = end - beg;
    float inv = (deg > 0) ? 1.f / (float)deg : 0.f;
    a0.x *= inv; a0.y *= inv; a0.z *= inv; a0.w *= inv;
    float4* o = reinterpret_cast<float4*>(mean + (size_t)w * HH);
    o[lane] = a0;
    if (tail) {
        a1.x *= inv; a1.y *= inv; a1.z *= inv; a1.w *= inv;
        o[32 + lane] = a1;
    }
}

// ---------------- WMMA bf16-split GEMM ----------------
// C[:, cbase:cbase+BN] = act( sum_t A_t[M,K] @ W_t[K,BN] + bias )
// BM=128, BK=32 chunk. A,W split into bf16 hi+lo; acc += AhWh + AhWl + AlWh (fp32).
template <int BN, bool RELU>
__global__ __launch_bounds__(256) void mm_gemm(
    const float* __restrict__ A0, const float* __restrict__ W0,
    const float* __restrict__ A1, const float* __restrict__ W1,
    const float* __restrict__ A2, const float* __restrict__ W2,
    const float* __restrict__ bias, float* __restrict__ C,
    int M, int K, int ldC, int cbase, int nterms)
{
    constexpr int TN16 = BN / 16;
    constexpr int WN = (BN == 160) ? 2 : 1;   // warps along N
    constexpr int WM = 8 / WN;                // warps along M
    constexpr int MT = 128 / (16 * WM);       // m16 tiles per warp
    constexpr int NT = TN16 / WN;             // n16 tiles per warp
    constexpr int LDA = 40;                   // 32 + 8 pad (bf16)
    constexpr int LDB = BN + 8;

    extern __shared__ char sm[];
    __nv_bfloat16* sAh = reinterpret_cast<__nv_bfloat16*>(sm);
    __nv_bfloat16* sAl = sAh + 128 * LDA;
    __nv_bfloat16* sBh = sAl + 128 * LDA;
    __nv_bfloat16* sBl = sBh + 32 * LDB;
    float* sstage = reinterpret_cast<float*>(sBl + 32 * LDB);

    const int tid = threadIdx.x;
    const int wid = tid >> 5;
    const int lane = tid & 31;
    const int rowbase = blockIdx.x * 128;
    const int warp_m = wid % WM;
    const int warp_n = wid / WM;
    const int nbase = warp_n * NT * 16;

    wmma::fragment<wmma::accumulator, 16, 16, 16, float> acc[MT][NT];
    #pragma unroll
    for (int i = 0; i < MT; i++)
        #pragma unroll
        for (int j = 0; j < NT; j++) wmma::fill_fragment(acc[i][j], 0.f);

    const bool vec = (K % 32 == 0);

    for (int term = 0; term < nterms; term++) {
        const float* A = (term == 0) ? A0 : (term == 1) ? A1 : A2;
        const float* W = (term == 0) ? W0 : (term == 1) ? W1 : W2;
        const int nck = (K + 31) >> 5;

        for (int ck = 0; ck < nck; ck++) {
            const int kt = ck * 32;
            // ---- stage A tile [128 x 32] as bf16 hi/lo ----
            if (vec) {
                #pragma unroll
                for (int p = 0; p < 4; p++) {
                    int idx = tid + 256 * p;       // 1024 quads
                    int r = idx >> 3, kq = idx & 7;
                    int gr = rowbase + r;
                    float4 v = make_float4(0.f, 0.f, 0.f, 0.f);
                    if (gr < M)
                        v = *reinterpret_cast<const float4*>(A + (size_t)gr * K + kt + kq * 4);
                    float xs[4] = {v.x, v.y, v.z, v.w};
                    #pragma unroll
                    for (int u = 0; u < 4; u++) {
                        __nv_bfloat16 hi = __float2bfloat16(xs[u]);
                        __nv_bfloat16 lo = __float2bfloat16(xs[u] - __bfloat162float(hi));
                        sAh[r * LDA + kq * 4 + u] = hi;
                        sAl[r * LDA + kq * 4 + u] = lo;
                    }
                }
            } else {
                for (int idx = tid; idx < 128 * 32; idx += 256) {
                    int r = idx >> 5, c = idx & 31;
                    int gr = rowbase + r, gk = kt + c;
                    float x = (gr < M && gk < K) ? A[(size_t)gr * K + gk] : 0.f;
                    __nv_bfloat16 hi = __float2bfloat16(x);
                    __nv_bfloat16 lo = __float2bfloat16(x - __bfloat162float(hi));
                    sAh[r * LDA + c] = hi;
                    sAl[r * LDA + c] = lo;
                }
            }
            // ---- stage W tile [32 x BN] as bf16 hi/lo ----
            {
                constexpr int QU = 8 * BN;         // 32*BN/4 quads
                for (int idx = tid; idx < QU; idx += 256) {
                    int r = idx / (BN / 4);
                    int cq = idx % (BN / 4);
                    int gk = kt + r;
                    float4 v = make_float4(0.f, 0.f, 0.f, 0.f);
                    if (gk < K)
                        v = *reinterpret_cast<const float4*>(W + (size_t)gk * BN + cq * 4);
                    float xs[4] = {v.x, v.y, v.z, v.w};
                    #pragma unroll
                    for (int u = 0; u < 4; u++) {
                        __nv_bfloat16 hi = __float2bfloat16(xs[u]);
                        __nv_bfloat16 lo = __float2bfloat16(xs[u] - __bfloat162float(hi));
                        sBh[r * LDB + cq * 4 + u] = hi;
                        sBl[r * LDB + cq * 4 + u] = lo;
                    }
                }
            }
            __syncthreads();

            // ---- 2 k16 steps, 3-product split MMA ----
            #pragma unroll
            for (int ks = 0; ks < 2; ks++) {
                wmma::fragment<wmma::matrix_a, 16, 16, 16, __nv_bfloat16, wmma::row_major> ah[MT], al[MT];
                #pragma unroll
                for (int i = 0; i < MT; i++) {
                    int r0 = (warp_m * MT + i) * 16;
                    wmma::load_matrix_sync(ah[i], sAh + r0 * LDA + ks * 16, LDA);
                    wmma::load_matrix_sync(al[i], sAl + r0 * LDA + ks * 16, LDA);
                }
                wmma::fragment<wmma::matrix_b, 16, 16, 16, __nv_bfloat16, wmma::row_major> bh[NT], bl[NT];
                #pragma unroll
                for (int j = 0; j < NT; j++) {
                    wmma::load_matrix_sync(bh[j], sBh + ks * 16 * LDB + nbase + j * 16, LDB);
                    wmma::load_matrix_sync(bl[j], sBl + ks * 16 * LDB + nbase + j * 16, LDB);
                }
                #pragma unroll
                for (int i = 0; i < MT; i++)
                    #pragma unroll
                    for (int j = 0; j < NT; j++) {
                        wmma::mma_sync(acc[i][j], ah[i], bh[j], acc[i][j]);
                        wmma::mma_sync(acc[i][j], ah[i], bl[j], acc[i][j]);
                        wmma::mma_sync(acc[i][j], al[i], bh[j], acc[i][j]);
                    }
            }
            __syncthreads();
        }
    }

    // ---- epilogue: per-warp 16x16 stage -> bias + leaky + float4 stores ----
    float* st = sstage + wid * 256;
    #pragma unroll
    for (int i = 0; i < MT; i++) {
        #pragma unroll
        for (int j = 0; j < NT; j++) {
            wmma::store_matrix_sync(st, acc[i][j], 16, wmma::mem_row_major);
            __syncwarp();
            int r = lane >> 1;
            int c0 = (lane & 1) * 8;
            int grow = rowbase + (warp_m * MT + i) * 16 + r;
            if (grow < M) {
                int cloc = nbase + j * 16 + c0;
                float* cp = C + (size_t)grow * ldC + cbase + cloc;
                #pragma unroll
                for (int q = 0; q < 2; q++) {
                    float4 v;
                    v.x = st[r * 16 + c0 + q * 4 + 0] + bias[cloc + q * 4 + 0];
                    v.y = st[r * 16 + c0 + q * 4 + 1] + bias[cloc + q * 4 + 1];
                    v.z = st[r * 16 + c0 + q * 4 + 2] + bias[cloc + q * 4 + 2];
                    v.w = st[r * 16 + c0 + q * 4 + 3] + bias[cloc + q * 4 + 3];
                    if (RELU) {
                        v.x = (v.x >= 0.f) ? v.x : LEAK * v.x;
                        v.y = (v.y >= 0.f) ? v.y : LEAK * v.y;
                        v.z = (v.z >= 0.f) ? v.z : LEAK * v.z;
                        v.w = (v.w >= 0.f) ? v.w : LEAK * v.w;
                    }
                    *reinterpret_cast<float4*>(cp + q * 4) = v;
                }
            }
            __syncwarp();
        }
    }
}

// ---------------- final tiny head: out = em @ W_o2 + b_o2 ----------------
__global__ void k_out2(const float* __restrict__ em, const float* __restrict__ W2,
                       const float* __restrict__ b2, float* __restrict__ out) {
    __shared__ float es[64 * 80];
    int nb = blockIdx.x * 64;
    for (int idx = threadIdx.x; idx < 64 * 80; idx += 256) {
        int n = nb + idx / 80;
        es[idx] = (n < NN) ? em[(size_t)n * 80 + idx % 80] : 0.f;
    }
    __syncthreads();
    int t = threadIdx.x;
    if (t < 128) {
        int ln = t >> 1;
        int c = t & 1;
        int n = nb + ln;
        if (n < NN) {
            float s = b2[c];
            #pragma unroll 8
            for (int k = 0; k < 80; k++) s += es[ln * 80 + k] * W2[k * 2 + c];
            out[(size_t)n * 2 + c] = s;
        }
    }
}

// smem bytes for mm_gemm<BN,...>
static int smem_bytes(int BN) {
    int LDB = BN + 8;
    return 2 * (128 * 40 * 2) + 2 * (32 * LDB * 2) + 8 * 256 * 4;
}

// ---------------- launch ----------------
extern "C" void kernel_launch(void* const* d_in, const int* in_sizes, int n_in,
                              void* d_out, int out_size) {
    const float* pre_x   = (const float*)d_in[0];
    const int*   ei      = (const int*)d_in[2];
    const int*   et      = (const int*)d_in[3];
    const float* numprop = (const float*)d_in[4];
    const float* numcat  = (const float*)d_in[5];
    const float* des     = (const float*)d_in[6];
    const float* tweet   = (const float*)d_in[7];
    const float* W_np = (const float*)d_in[8],  *b_np = (const float*)d_in[9];
    const float* W_nc = (const float*)d_in[10], *b_nc = (const float*)d_in[11];
    const float* W_des = (const float*)d_in[12], *b_des = (const float*)d_in[13];
    const float* W_text = (const float*)d_in[14], *b_text = (const float*)d_in[15];
    const float* W_tweet = (const float*)d_in[16], *b_tweet = (const float*)d_in[17];
    const float* W_in = (const float*)d_in[18], *b_in = (const float*)d_in[19];
    const float* W_rel1 = (const float*)d_in[20];
    const float* W_root1 = (const float*)d_in[21], *b_conv1 = (const float*)d_in[22];
    const float* W_rel2 = (const float*)d_in[23];
    const float* W_root2 = (const float*)d_in[24], *b_conv2 = (const float*)d_in[25];
    const float* W_o1 = (const float*)d_in[26], *b_o1 = (const float*)d_in[27];
    const float* W_o2 = (const float*)d_in[28], *b_o2 = (const float*)d_in[29];

    float* t;    cudaGetSymbolAddress((void**)&t, g_t);
    float* hA;   cudaGetSymbolAddress((void**)&hA, g_hA);
    float* hB;   cudaGetSymbolAddress((void**)&hB, g_hB);
    float* mean; cudaGetSymbolAddress((void**)&mean, g_mean);

    float* out = (float*)d_out;            // [N,2]
    float* em = out + 2 * (size_t)NN;      // [N,80]

    const int SM160 = smem_bytes(160);     // 50176
    const int SM80  = smem_bytes(80);      // 39936
    const int SM32  = smem_bytes(32);      // 33792
    cudaFuncSetAttribute(mm_gemm<32, true>,   cudaFuncAttributeMaxDynamicSharedMemorySize, SM32);
    cudaFuncSetAttribute(mm_gemm<160, true>,  cudaFuncAttributeMaxDynamicSharedMemorySize, SM160);
    cudaFuncSetAttribute(mm_gemm<160, false>, cudaFuncAttributeMaxDynamicSharedMemorySize, SM160);
    cudaFuncSetAttribute(mm_gemm<80, true>,   cudaFuncAttributeMaxDynamicSharedMemorySize, SM80);

    // CSR build
    k_zero_deg<<<(2 * NN + 255) / 256, 256>>>();
    k_count<<<(EE + 255) / 256, 256>>>(ei, et);
    k_scan<<<1, 1024>>>();
    k_fill<<<(EE + 255) / 256, 256>>>(ei, et);

    dim3 gM((NN + 127) / 128);

    // encoders -> g_t  (concat: np | nc | des | tweet@W_text | pre_x@W_tweet)
    mm_gemm<32, true><<<gM, 256, SM32>>>(numprop, W_np, nullptr, nullptr, nullptr, nullptr,
                                         b_np, t, NN, 6, HH, 0, 1);
    mm_gemm<32, true><<<gM, 256, SM32>>>(numcat, W_nc, nullptr, nullptr, nullptr, nullptr,
                                         b_nc, t, NN, 11, HH, 32, 1);
    mm_gemm<32, true><<<gM, 256, SM32>>>(des, W_des, nullptr, nullptr, nullptr, nullptr,
                                         b_des, t, NN, 768, HH, 64, 1);
    mm_gemm<32, true><<<gM, 256, SM32>>>(tweet, W_text, nullptr, nullptr, nullptr, nullptr,
                                         b_text, t, NN, 768, HH, 96, 1);
    mm_gemm<32, true><<<gM, 256, SM32>>>(pre_x, W_tweet, nullptr, nullptr, nullptr, nullptr,
                                         b_tweet, t, NN, 768, HH, 128, 1);

    // h = leaky(t @ W_in + b_in)
    mm_gemm<160, true><<<gM, 256, SM160>>>(t, W_in, nullptr, nullptr, nullptr, nullptr,
                                           b_in, hA, NN, HH, HH, 0, 1);

    // conv1
    k_gather<<<(2 * NN * 32 + 255) / 256, 256>>>(hA, mean);
    mm_gemm<160, false><<<gM, 256, SM160>>>(hA, W_root1,
                                            mean, W_rel1,
                                            mean + (size_t)NN * HH, W_rel1 + HH * HH,
                                            b_conv1, hB, NN, HH, HH, 0, 3);

    // conv2
    k_gather<<<(2 * NN * 32 + 255) / 256, 256>>>(hB, mean);
    mm_gemm<160, false><<<gM, 256, SM160>>>(hB, W_root2,
                                            mean, W_rel2,
                                            mean + (size_t)NN * HH, W_rel2 + HH * HH,
                                            b_conv2, hA, NN, HH, HH, 0, 3);

    // em = leaky(h @ W_o1 + b_o1)
    mm_gemm<80, true><<<gM, 256, SM80>>>(hA, W_o1, nullptr, nullptr, nullptr, nullptr,
                                         b_o1, em, NN, HH, 80, 0, 1);

    // out = em @ W_o2 + b_o2
    k_out2<<<(NN + 63) / 64, 256>>>(em, W_o2, b_o2, out);
}